// round 10
// baseline (speedup 1.0000x reference)
#include <cuda_runtime.h>
#include <cuda_fp16.h>
#include <mma.h>

using namespace nvcuda;

#define NNODES 100000
#define NEDGES 3200000
#define FIN 512
#define FOUT 256
#define TOTE (NEDGES + NNODES)

// ---------------- scratch (device globals; zero-init bss) ----------------
__device__ __align__(16) __half g_h0h[(size_t)NNODES * FOUT];  // fp16 h0 (z0 + blend)
__device__ __align__(16) __half g_zh0[(size_t)NNODES * FOUT];  // fp16 ping
__device__ __align__(16) __half g_zh1[(size_t)NNODES * FOUT];  // fp16 pong
__device__ int   g_cnt[NNODES];
__device__ float g_dinv[NNODES];
__device__ int   g_rowptr[NNODES + 1];
__device__ int   g_fill[NNODES];
__device__ int   g_bsum[512];
__device__ __align__(16) int2 g_edge[TOTE];   // (src, norm-as-int)
__device__ int   g_is64;

// ---------------- edge dtype detection ----------------
__global__ void k_detect(const int* __restrict__ e32, int E) {
    __shared__ int nz;
    if (threadIdx.x == 0) nz = 0;
    __syncthreads();
    int lim = min(E, 65536);
    for (int i = threadIdx.x; i < lim; i += blockDim.x)
        if (e32[2 * i + 1] != 0) nz = 1;   // benign race
    __syncthreads();
    if (threadIdx.x == 0) g_is64 = (nz == 0) ? 1 : 0;
}

__device__ __forceinline__ int edge_at(const void* ei, long long idx) {
    if (g_is64) return (int)((const long long*)ei)[idx];
    return ((const int*)ei)[idx];
}

// ---------------- graph preprocessing ----------------
__global__ void k_zero(int n) {
    int i = blockIdx.x * blockDim.x + threadIdx.x;
    if (i < n) g_cnt[i] = 0;
}

__global__ void k_count(const void* __restrict__ ei, int E, int n) {
    int i = blockIdx.x * blockDim.x + threadIdx.x;
    if (i < E) {
        int d = edge_at(ei, (long long)E + i);
        d = min(max(d, 0), n - 1);
        atomicAdd(&g_cnt[d], 1);
    }
}

__global__ void k_dinv(int n) {
    int i = blockIdx.x * blockDim.x + threadIdx.x;
    if (i < n) {
        int c = g_cnt[i] + 1;               // + self loop
        g_cnt[i] = c;
        g_dinv[i] = rsqrtf((float)c);
    }
}

__global__ void k_scanA(int n) {
    __shared__ int sh[256];
    int tid = threadIdx.x;
    int i = blockIdx.x * 256 + tid;
    int v = (i < n) ? g_cnt[i] : 0;
    sh[tid] = v;
    __syncthreads();
    for (int off = 1; off < 256; off <<= 1) {
        int t = (tid >= off) ? sh[tid - off] : 0;
        __syncthreads();
        sh[tid] += t;
        __syncthreads();
    }
    if (i < n) g_rowptr[i] = sh[tid] - v;
    if (tid == 255) g_bsum[blockIdx.x] = sh[255];
}

__global__ void k_scanB(int nb) {
    __shared__ int sh[512];
    int tid = threadIdx.x;
    int v = (tid < nb) ? g_bsum[tid] : 0;
    sh[tid] = v;
    __syncthreads();
    for (int off = 1; off < 512; off <<= 1) {
        int t = (tid >= off) ? sh[tid - off] : 0;
        __syncthreads();
        sh[tid] += t;
        __syncthreads();
    }
    g_bsum[tid] = sh[tid] - v;
}

__global__ void k_scanC(int n, int total) {
    int i = blockIdx.x * blockDim.x + threadIdx.x;
    if (i < n) {
        g_rowptr[i] += g_bsum[i >> 8];
        g_fill[i] = 0;
    }
    if (i == 0) g_rowptr[n] = total;
}

__global__ void k_scatter(const void* __restrict__ ei, int E, int n) {
    int i = blockIdx.x * blockDim.x + threadIdx.x;
    int tot = E + n;
    if (i >= tot) return;
    int s, d;
    if (i < E) {
        s = edge_at(ei, i);
        d = edge_at(ei, (long long)E + i);
        s = min(max(s, 0), n - 1);
        d = min(max(d, 0), n - 1);
    } else {
        s = d = i - E;
    }
    int pos = g_rowptr[d] + atomicAdd(&g_fill[d], 1);
    pos = min(max(pos, 0), tot - 1);
    float w = g_dinv[s] * g_dinv[d];
    g_edge[pos] = make_int2(s, __float_as_int(w));
}

// -------- tensor-core GEMM + bias + L2-normalize*1.8 -> g_h0h (fp16) --------
// Block: 128 rows x 256 cols, 8 warps, warp owns 16 rows. BK=32.
__global__ __launch_bounds__(256) void k_gemm_tc(const float* __restrict__ x,
                                                 const float* __restrict__ W,
                                                 const float* __restrict__ b,
                                                 int N) {
    __shared__ __align__(16) __half Ah[128][32];
    __shared__ __align__(16) __half Bh[256][32];
    __shared__ __align__(16) float  scr[8][256];
    __shared__ float bsh[256];

    int tid  = threadIdx.x;
    int w    = tid >> 5;
    int lane = tid & 31;
    int rows0 = blockIdx.x * 128;

    bsh[tid] = b[tid];

    wmma::fragment<wmma::accumulator, 16, 16, 16, float> acc[16];
#pragma unroll
    for (int n = 0; n < 16; n++) wmma::fill_fragment(acc[n], 0.0f);

    for (int k0 = 0; k0 < FIN; k0 += 32) {
        // stage x tile (128x32) -> fp16
        {
            int r = tid >> 1;
            int part = (tid & 1) * 16;
            int grow = rows0 + r;
            float4 v0 = make_float4(0.f,0.f,0.f,0.f), v1 = v0, v2 = v0, v3 = v0;
            if (grow < N) {
                const float* xp = &x[(size_t)grow * FIN + k0 + part];
                v0 = *(const float4*)xp;
                v1 = *(const float4*)(xp + 4);
                v2 = *(const float4*)(xp + 8);
                v3 = *(const float4*)(xp + 12);
            }
            __half2 h0 = __floats2half2_rn(v0.x, v0.y);
            __half2 h1 = __floats2half2_rn(v0.z, v0.w);
            __half2 h2 = __floats2half2_rn(v1.x, v1.y);
            __half2 h3 = __floats2half2_rn(v1.z, v1.w);
            __half2 h4 = __floats2half2_rn(v2.x, v2.y);
            __half2 h5 = __floats2half2_rn(v2.z, v2.w);
            __half2 h6 = __floats2half2_rn(v3.x, v3.y);
            __half2 h7 = __floats2half2_rn(v3.z, v3.w);
            uint4 a, c;
            a.x = *(unsigned*)&h0; a.y = *(unsigned*)&h1;
            a.z = *(unsigned*)&h2; a.w = *(unsigned*)&h3;
            c.x = *(unsigned*)&h4; c.y = *(unsigned*)&h5;
            c.z = *(unsigned*)&h6; c.w = *(unsigned*)&h7;
            *(uint4*)&Ah[r][part]     = a;
            *(uint4*)&Ah[r][part + 8] = c;
        }
        // stage W tile (256x32) -> fp16
        {
            const float* wp = &W[(size_t)tid * FIN + k0];
#pragma unroll
            for (int q = 0; q < 2; q++) {
                float4 w0 = *(const float4*)(wp + q * 16);
                float4 w1 = *(const float4*)(wp + q * 16 + 4);
                float4 w2 = *(const float4*)(wp + q * 16 + 8);
                float4 w3 = *(const float4*)(wp + q * 16 + 12);
                __half2 h0 = __floats2half2_rn(w0.x, w0.y);
                __half2 h1 = __floats2half2_rn(w0.z, w0.w);
                __half2 h2 = __floats2half2_rn(w1.x, w1.y);
                __half2 h3 = __floats2half2_rn(w1.z, w1.w);
                __half2 h4 = __floats2half2_rn(w2.x, w2.y);
                __half2 h5 = __floats2half2_rn(w2.z, w2.w);
                __half2 h6 = __floats2half2_rn(w3.x, w3.y);
                __half2 h7 = __floats2half2_rn(w3.z, w3.w);
                uint4 a, c;
                a.x = *(unsigned*)&h0; a.y = *(unsigned*)&h1;
                a.z = *(unsigned*)&h2; a.w = *(unsigned*)&h3;
                c.x = *(unsigned*)&h4; c.y = *(unsigned*)&h5;
                c.z = *(unsigned*)&h6; c.w = *(unsigned*)&h7;
                *(uint4*)&Bh[tid][q * 16]     = a;
                *(uint4*)&Bh[tid][q * 16 + 8] = c;
            }
        }
        __syncthreads();

#pragma unroll
        for (int kk = 0; kk < 2; kk++) {
            wmma::fragment<wmma::matrix_a, 16, 16, 16, __half, wmma::row_major> af;
            wmma::load_matrix_sync(af, &Ah[w * 16][kk * 16], 32);
#pragma unroll
            for (int n = 0; n < 16; n++) {
                wmma::fragment<wmma::matrix_b, 16, 16, 16, __half, wmma::col_major> bf;
                wmma::load_matrix_sync(bf, &Bh[n * 16][kk * 16], 32);
                wmma::mma_sync(acc[n], af, bf, acc[n]);
            }
        }
        __syncthreads();
    }

    // epilogue: bias + row L2 norm + scale, write fp16
    float* sc = scr[w];
    int lrow  = lane >> 1;
    int lcol0 = (lane & 1) * 8;
    float ssq = 0.0f;
#pragma unroll
    for (int n = 0; n < 16; n++) {
        wmma::store_matrix_sync(sc, acc[n], 16, wmma::mem_row_major);
        __syncwarp();
#pragma unroll
        for (int j = 0; j < 8; j++) {
            float v = sc[lrow * 16 + lcol0 + j] + bsh[n * 16 + lcol0 + j];
            ssq += v * v;
        }
        __syncwarp();
    }
    ssq += __shfl_xor_sync(0xffffffffu, ssq, 1);
    float scale = 1.8f / fmaxf(sqrtf(ssq), 1e-12f);
    int grow = rows0 + w * 16 + lrow;
#pragma unroll
    for (int n = 0; n < 16; n++) {
        wmma::store_matrix_sync(sc, acc[n], 16, wmma::mem_row_major);
        __syncwarp();
        __half hv[8];
#pragma unroll
        for (int j = 0; j < 8; j++) {
            float v = (sc[lrow * 16 + lcol0 + j] + bsh[n * 16 + lcol0 + j]) * scale;
            hv[j] = __float2half_rn(v);
        }
        if (grow < N)
            *(uint4*)&g_h0h[(size_t)grow * FOUT + n * 16 + lcol0] = *(uint4*)hv;
        __syncwarp();
    }
}

// ---------------- APPNP step: one WARP per dst node, fp16 z ----------------
__device__ __forceinline__ void edge_accum(const __half* __restrict__ zin,
                                           int sj, float wj, int lane,
                                           float acc[8]) {
    uint4 v = *((const uint4*)(zin + (size_t)sj * FOUT) + lane);
    float2 f0 = __half22float2(*(__half2*)&v.x);
    float2 f1 = __half22float2(*(__half2*)&v.y);
    float2 f2 = __half22float2(*(__half2*)&v.z);
    float2 f3 = __half22float2(*(__half2*)&v.w);
    acc[0] += wj * f0.x; acc[1] += wj * f0.y;
    acc[2] += wj * f1.x; acc[3] += wj * f1.y;
    acc[4] += wj * f2.x; acc[5] += wj * f2.y;
    acc[6] += wj * f3.x; acc[7] += wj * f3.y;
}

__device__ __forceinline__ void prop_gather(const __half* __restrict__ zin,
                                            int node, int lane,
                                            float acc[8]) {
    int beg = g_rowptr[node];
    int end = g_rowptr[node + 1];
    int base = beg;
    // full 32-edge tiles: static bounds, unrolled for batched LDG issue
    for (; base + 32 <= end; base += 32) {
        int2 t = g_edge[base + lane];
        int   s = t.x;
        float w = __int_as_float(t.y);
#pragma unroll 4
        for (int j = 0; j < 32; j++) {
            int   sj = __shfl_sync(0xffffffffu, s, j);
            float wj = __shfl_sync(0xffffffffu, w, j);
            edge_accum(zin, sj, wj, lane, acc);
        }
    }
    // tail
    if (base < end) {
        int idx = base + lane;
        int   s = 0;
        float w = 0.f;
        if (idx < end) {
            int2 t = g_edge[idx];
            s = t.x;
            w = __int_as_float(t.y);
        }
        int cnt = end - base;
        for (int j = 0; j < cnt; j++) {
            int   sj = __shfl_sync(0xffffffffu, s, j);
            float wj = __shfl_sync(0xffffffffu, w, j);
            edge_accum(zin, sj, wj, lane, acc);
        }
    }
}

__device__ __forceinline__ const __half* pick_h(int sel) {
    return sel == 0 ? g_h0h : (sel == 1 ? g_zh0 : g_zh1);
}

__device__ __forceinline__ void blend_h0(int node, int lane, float a[8],
                                         float r[8]) {
    uint4 hv = *((const uint4*)(g_h0h + (size_t)node * FOUT) + lane);
    float2 f0 = __half22float2(*(__half2*)&hv.x);
    float2 f1 = __half22float2(*(__half2*)&hv.y);
    float2 f2 = __half22float2(*(__half2*)&hv.z);
    float2 f3 = __half22float2(*(__half2*)&hv.w);
    r[0] = 0.85f * a[0] + 0.15f * f0.x;
    r[1] = 0.85f * a[1] + 0.15f * f0.y;
    r[2] = 0.85f * a[2] + 0.15f * f1.x;
    r[3] = 0.85f * a[3] + 0.15f * f1.y;
    r[4] = 0.85f * a[4] + 0.15f * f2.x;
    r[5] = 0.85f * a[5] + 0.15f * f2.y;
    r[6] = 0.85f * a[6] + 0.15f * f3.x;
    r[7] = 0.85f * a[7] + 0.15f * f3.y;
}

__global__ __launch_bounds__(256) void k_proph(int insel, int outsel) {
    const __half* zin = pick_h(insel);
    __half* zout = (outsel == 1) ? g_zh0 : g_zh1;
    int warp = threadIdx.x >> 5;
    int lane = threadIdx.x & 31;
    int node = blockIdx.x * 8 + warp;
    if (node >= NNODES) return;

    float a[8];
#pragma unroll
    for (int i = 0; i < 8; i++) a[i] = 0.f;
    prop_gather(zin, node, lane, a);

    float r[8];
    blend_h0(node, lane, a, r);
    __half2 h01 = __floats2half2_rn(r[0], r[1]);
    __half2 h23 = __floats2half2_rn(r[2], r[3]);
    __half2 h45 = __floats2half2_rn(r[4], r[5]);
    __half2 h67 = __floats2half2_rn(r[6], r[7]);
    uint4 hv;
    hv.x = *(unsigned*)&h01; hv.y = *(unsigned*)&h23;
    hv.z = *(unsigned*)&h45; hv.w = *(unsigned*)&h67;
    *((uint4*)(zout + (size_t)node * FOUT) + lane) = hv;
}

__global__ __launch_bounds__(256) void k_propf(int insel, float* __restrict__ dout) {
    const __half* zin = pick_h(insel);
    int warp = threadIdx.x >> 5;
    int lane = threadIdx.x & 31;
    int node = blockIdx.x * 8 + warp;
    if (node >= NNODES) return;

    float a[8];
#pragma unroll
    for (int i = 0; i < 8; i++) a[i] = 0.f;
    prop_gather(zin, node, lane, a);

    float r[8];
    blend_h0(node, lane, a, r);
    float4* op = (float4*)(dout + (size_t)node * FOUT);
    op[lane * 2]     = make_float4(r[0], r[1], r[2], r[3]);
    op[lane * 2 + 1] = make_float4(r[4], r[5], r[6], r[7]);
}

// ---------------- launch ----------------
extern "C" void kernel_launch(void* const* d_in, const int* in_sizes, int n_in,
                              void* d_out, int out_size) {
    const float* x  = 0;
    const void*  ei = 0;
    const float* W1 = 0;
    const float* b1 = 0;
    for (int i = 0; i < n_in; i++) {
        int sz = in_sizes[i];
        if      (sz == NNODES * FIN) x  = (const float*)d_in[i];
        else if (sz == 2 * NEDGES)   ei = d_in[i];
        else if (sz == FOUT * FIN)   W1 = (const float*)d_in[i];
        else if (sz == FOUT)         b1 = (const float*)d_in[i];
    }
    float* out = (float*)d_out;
    int N = NNODES;
    int E = NEDGES;

    k_detect<<<1, 256>>>((const int*)ei, E);
    k_zero<<<(N + 255) / 256, 256>>>(N);
    k_count<<<(E + 255) / 256, 256>>>(ei, E, N);
    k_dinv<<<(N + 255) / 256, 256>>>(N);
    int nb = (N + 255) / 256;
    k_scanA<<<nb, 256>>>(N);
    k_scanB<<<1, 512>>>(nb);
    k_scanC<<<(N + 255) / 256, 256>>>(N, E + N);
    k_scatter<<<(E + N + 255) / 256, 256>>>(ei, E, N);

    k_gemm_tc<<<(N + 127) / 128, 256>>>(x, W1, b1, N);

    // APPNP in fp16: step k writes (k even -> g_zh0, k odd -> g_zh1);
    // k=0 reads g_h0h; k=9 reads g_zh0 and writes fp32 d_out.
    int nprop = (N + 7) / 8;
    for (int k = 0; k < 9; k++) {
        int insel  = (k == 0) ? 0 : (((k - 1) & 1) ? 2 : 1);
        int outsel = (k & 1) ? 2 : 1;
        k_proph<<<nprop, 256>>>(insel, outsel);
    }
    k_propf<<<nprop, 256>>>(1, out);   // k=8 wrote g_zh0
}

// round 11
// speedup vs baseline: 1.1757x; 1.1757x over previous
#include <cuda_runtime.h>
#include <cuda_fp16.h>
#include <mma.h>

using namespace nvcuda;

#define NNODES 100000
#define NEDGES 3200000
#define FIN 512
#define FOUT 256
#define TOTE (NEDGES + NNODES)

// ---------------- scratch (device globals; zero-init bss) ----------------
__device__ __align__(16) __half g_h0h[(size_t)NNODES * FOUT];  // fp16 h0 (z0 + blend)
__device__ __align__(16) __half g_zh0[(size_t)NNODES * FOUT];  // fp16 ping
__device__ __align__(16) __half g_zh1[(size_t)NNODES * FOUT];  // fp16 pong
__device__ int   g_cnt[NNODES];
__device__ float g_dinv[NNODES];
__device__ int   g_rowptr[NNODES + 1];
__device__ int   g_fill[NNODES];
__device__ int   g_bsum[512];
__device__ __align__(16) int2 g_edge[TOTE];   // (src, norm-as-int)
__device__ int   g_is64;

// ---------------- edge dtype detection ----------------
__global__ void k_detect(const int* __restrict__ e32, int E) {
    __shared__ int nz;
    if (threadIdx.x == 0) nz = 0;
    __syncthreads();
    int lim = min(E, 65536);
    for (int i = threadIdx.x; i < lim; i += blockDim.x)
        if (e32[2 * i + 1] != 0) nz = 1;   // benign race
    __syncthreads();
    if (threadIdx.x == 0) g_is64 = (nz == 0) ? 1 : 0;
}

__device__ __forceinline__ int edge_at(const void* ei, long long idx) {
    if (g_is64) return (int)((const long long*)ei)[idx];
    return ((const int*)ei)[idx];
}

// ---------------- graph preprocessing ----------------
__global__ void k_zero(int n) {
    int i = blockIdx.x * blockDim.x + threadIdx.x;
    if (i < n) { g_cnt[i] = 0; g_fill[i] = 0; }
}

__global__ void k_count(const void* __restrict__ ei, int E, int n) {
    int i = blockIdx.x * blockDim.x + threadIdx.x;
    if (i < E) {
        int d = edge_at(ei, (long long)E + i);
        d = min(max(d, 0), n - 1);
        atomicAdd(&g_cnt[d], 1);
    }
}

__global__ void k_dinv(int n) {
    int i = blockIdx.x * blockDim.x + threadIdx.x;
    if (i < n) {
        int c = g_cnt[i] + 1;               // + self loop
        g_cnt[i] = c;
        g_dinv[i] = rsqrtf((float)c);
    }
}

__global__ void k_scanA(int n) {
    __shared__ int sh[256];
    int tid = threadIdx.x;
    int i = blockIdx.x * 256 + tid;
    int v = (i < n) ? g_cnt[i] : 0;
    sh[tid] = v;
    __syncthreads();
    for (int off = 1; off < 256; off <<= 1) {
        int t = (tid >= off) ? sh[tid - off] : 0;
        __syncthreads();
        sh[tid] += t;
        __syncthreads();
    }
    if (i < n) g_rowptr[i] = sh[tid] - v;
    if (tid == 255) g_bsum[blockIdx.x] = sh[255];
}

__global__ void k_scanB(int nb) {
    __shared__ int sh[512];
    int tid = threadIdx.x;
    int v = (tid < nb) ? g_bsum[tid] : 0;
    sh[tid] = v;
    __syncthreads();
    for (int off = 1; off < 512; off <<= 1) {
        int t = (tid >= off) ? sh[tid - off] : 0;
        __syncthreads();
        sh[tid] += t;
        __syncthreads();
    }
    g_bsum[tid] = sh[tid] - v;
}

__global__ void k_scanC(int n, int total) {
    int i = blockIdx.x * blockDim.x + threadIdx.x;
    if (i < n) g_rowptr[i] += g_bsum[i >> 8];
    if (i == 0) g_rowptr[n] = total;
}

__global__ void k_scatter(const void* __restrict__ ei, int E, int n) {
    int i = blockIdx.x * blockDim.x + threadIdx.x;
    int tot = E + n;
    if (i >= tot) return;
    int s, d;
    if (i < E) {
        s = edge_at(ei, i);
        d = edge_at(ei, (long long)E + i);
        s = min(max(s, 0), n - 1);
        d = min(max(d, 0), n - 1);
    } else {
        s = d = i - E;
    }
    int pos = g_rowptr[d] + atomicAdd(&g_fill[d], 1);
    pos = min(max(pos, 0), tot - 1);
    float w = g_dinv[s] * g_dinv[d];
    g_edge[pos] = make_int2(s, __float_as_int(w));
}

// -------- tensor-core GEMM + bias + L2-normalize*1.8 -> g_h0h (fp16) --------
// Block: 128 rows x 256 cols, 8 warps, each warp owns 16 full rows.
// BK=16; fp16 inputs (converted on stage-in), fp32 accumulate.
__global__ __launch_bounds__(256) void k_gemm_tc(const float* __restrict__ x,
                                                 const float* __restrict__ W,
                                                 const float* __restrict__ b,
                                                 int N) {
    __shared__ __align__(16) __half Ah[128][16];
    __shared__ __align__(16) __half Bh[256][16];
    __shared__ __align__(16) float  scr[8][256];   // per-warp 16x16 scratch
    __shared__ float bsh[256];

    int tid  = threadIdx.x;
    int w    = tid >> 5;
    int lane = tid & 31;
    int rows0 = blockIdx.x * 128;

    bsh[tid] = b[tid];

    wmma::fragment<wmma::accumulator, 16, 16, 16, float> acc[16];
#pragma unroll
    for (int n = 0; n < 16; n++) wmma::fill_fragment(acc[n], 0.0f);

    for (int k0 = 0; k0 < FIN; k0 += 16) {
        // stage x tile (128x16) -> fp16
        {
            int r = tid >> 1;
            int part = tid & 1;          // 0 or 1, 8 cols each
            int grow = rows0 + r;
            float4 v0 = make_float4(0.f, 0.f, 0.f, 0.f);
            float4 v1 = v0;
            if (grow < N) {
                const float* xp = &x[(size_t)grow * FIN + k0 + part * 8];
                v0 = *(const float4*)xp;
                v1 = *(const float4*)(xp + 4);
            }
            __half2 h0 = __floats2half2_rn(v0.x, v0.y);
            __half2 h1 = __floats2half2_rn(v0.z, v0.w);
            __half2 h2 = __floats2half2_rn(v1.x, v1.y);
            __half2 h3 = __floats2half2_rn(v1.z, v1.w);
            uint4 hv;
            hv.x = *(unsigned*)&h0; hv.y = *(unsigned*)&h1;
            hv.z = *(unsigned*)&h2; hv.w = *(unsigned*)&h3;
            *(uint4*)&Ah[r][part * 8] = hv;
        }
        // stage W tile (256x16) -> fp16
        {
            const float* wp = &W[(size_t)tid * FIN + k0];
            float4 w0 = *(const float4*)(wp);
            float4 w1 = *(const float4*)(wp + 4);
            float4 w2 = *(const float4*)(wp + 8);
            float4 w3 = *(const float4*)(wp + 12);
            __half2 h0 = __floats2half2_rn(w0.x, w0.y);
            __half2 h1 = __floats2half2_rn(w0.z, w0.w);
            __half2 h2 = __floats2half2_rn(w1.x, w1.y);
            __half2 h3 = __floats2half2_rn(w1.z, w1.w);
            __half2 h4 = __floats2half2_rn(w2.x, w2.y);
            __half2 h5 = __floats2half2_rn(w2.z, w2.w);
            __half2 h6 = __floats2half2_rn(w3.x, w3.y);
            __half2 h7 = __floats2half2_rn(w3.z, w3.w);
            uint4 a, c;
            a.x = *(unsigned*)&h0; a.y = *(unsigned*)&h1;
            a.z = *(unsigned*)&h2; a.w = *(unsigned*)&h3;
            c.x = *(unsigned*)&h4; c.y = *(unsigned*)&h5;
            c.z = *(unsigned*)&h6; c.w = *(unsigned*)&h7;
            *(uint4*)&Bh[tid][0] = a;
            *(uint4*)&Bh[tid][8] = c;
        }
        __syncthreads();

        wmma::fragment<wmma::matrix_a, 16, 16, 16, __half, wmma::row_major> af;
        wmma::load_matrix_sync(af, &Ah[w * 16][0], 16);
#pragma unroll
        for (int n = 0; n < 16; n++) {
            wmma::fragment<wmma::matrix_b, 16, 16, 16, __half, wmma::col_major> bf;
            wmma::load_matrix_sync(bf, &Bh[n * 16][0], 16);
            wmma::mma_sync(acc[n], af, bf, acc[n]);
        }
        __syncthreads();
    }

    // epilogue: bias + row L2 norm + scale, write fp16
    float* sc = scr[w];
    int lrow  = lane >> 1;          // 0..15 (warp-local row)
    int lcol0 = (lane & 1) * 8;     // 0 or 8 within 16-col frag
    float ssq = 0.0f;
#pragma unroll
    for (int n = 0; n < 16; n++) {
        wmma::store_matrix_sync(sc, acc[n], 16, wmma::mem_row_major);
        __syncwarp();
#pragma unroll
        for (int j = 0; j < 8; j++) {
            float v = sc[lrow * 16 + lcol0 + j] + bsh[n * 16 + lcol0 + j];
            ssq += v * v;
        }
        __syncwarp();
    }
    ssq += __shfl_xor_sync(0xffffffffu, ssq, 1);   // pair lanes complete the row
    float scale = 1.8f / fmaxf(sqrtf(ssq), 1e-12f);
    int grow = rows0 + w * 16 + lrow;
#pragma unroll
    for (int n = 0; n < 16; n++) {
        wmma::store_matrix_sync(sc, acc[n], 16, wmma::mem_row_major);
        __syncwarp();
        __half hv[8];
#pragma unroll
        for (int j = 0; j < 8; j++) {
            float v = (sc[lrow * 16 + lcol0 + j] + bsh[n * 16 + lcol0 + j]) * scale;
            hv[j] = __float2half_rn(v);
        }
        if (grow < N)
            *(uint4*)&g_h0h[(size_t)grow * FOUT + n * 16 + lcol0] = *(uint4*)hv;
        __syncwarp();
    }
}

// ---------------- APPNP step: one WARP per dst node, fp16 z ----------------
__device__ __forceinline__ void prop_gather(const __half* __restrict__ zin,
                                            int node, int lane,
                                            float acc[8]) {
    int beg = g_rowptr[node];
    int end = g_rowptr[node + 1];
    for (int base = beg; base < end; base += 32) {
        int idx = base + lane;
        int   s = 0;
        float w = 0.f;
        if (idx < end) {
            int2 t = g_edge[idx];
            s = t.x;
            w = __int_as_float(t.y);
        }
        int cnt = min(32, end - base);
        for (int j = 0; j < cnt; j++) {
            int   sj = __shfl_sync(0xffffffffu, s, j);
            float wj = __shfl_sync(0xffffffffu, w, j);
            uint4 v = *((const uint4*)(zin + (size_t)sj * FOUT) + lane);
            float2 f0 = __half22float2(*(__half2*)&v.x);
            float2 f1 = __half22float2(*(__half2*)&v.y);
            float2 f2 = __half22float2(*(__half2*)&v.z);
            float2 f3 = __half22float2(*(__half2*)&v.w);
            acc[0] += wj * f0.x; acc[1] += wj * f0.y;
            acc[2] += wj * f1.x; acc[3] += wj * f1.y;
            acc[4] += wj * f2.x; acc[5] += wj * f2.y;
            acc[6] += wj * f3.x; acc[7] += wj * f3.y;
        }
    }
}

__device__ __forceinline__ const __half* pick_h(int sel) {
    return sel == 0 ? g_h0h : (sel == 1 ? g_zh0 : g_zh1);
}

__device__ __forceinline__ void blend_h0(int node, int lane, float a[8],
                                         float r[8]) {
    uint4 hv = *((const uint4*)(g_h0h + (size_t)node * FOUT) + lane);
    float2 f0 = __half22float2(*(__half2*)&hv.x);
    float2 f1 = __half22float2(*(__half2*)&hv.y);
    float2 f2 = __half22float2(*(__half2*)&hv.z);
    float2 f3 = __half22float2(*(__half2*)&hv.w);
    r[0] = 0.85f * a[0] + 0.15f * f0.x;
    r[1] = 0.85f * a[1] + 0.15f * f0.y;
    r[2] = 0.85f * a[2] + 0.15f * f1.x;
    r[3] = 0.85f * a[3] + 0.15f * f1.y;
    r[4] = 0.85f * a[4] + 0.15f * f2.x;
    r[5] = 0.85f * a[5] + 0.15f * f2.y;
    r[6] = 0.85f * a[6] + 0.15f * f3.x;
    r[7] = 0.85f * a[7] + 0.15f * f3.y;
}

__global__ __launch_bounds__(256) void k_proph(int insel, int outsel) {
    const __half* zin = pick_h(insel);
    __half* zout = (outsel == 1) ? g_zh0 : g_zh1;
    int warp = threadIdx.x >> 5;
    int lane = threadIdx.x & 31;
    int node = blockIdx.x * 8 + warp;
    if (node >= NNODES) return;

    float a[8];
#pragma unroll
    for (int i = 0; i < 8; i++) a[i] = 0.f;
    prop_gather(zin, node, lane, a);

    float r[8];
    blend_h0(node, lane, a, r);
    __half2 h01 = __floats2half2_rn(r[0], r[1]);
    __half2 h23 = __floats2half2_rn(r[2], r[3]);
    __half2 h45 = __floats2half2_rn(r[4], r[5]);
    __half2 h67 = __floats2half2_rn(r[6], r[7]);
    uint4 hv;
    hv.x = *(unsigned*)&h01; hv.y = *(unsigned*)&h23;
    hv.z = *(unsigned*)&h45; hv.w = *(unsigned*)&h67;
    *((uint4*)(zout + (size_t)node * FOUT) + lane) = hv;
}

__global__ __launch_bounds__(256) void k_propf(int insel, float* __restrict__ dout) {
    const __half* zin = pick_h(insel);
    int warp = threadIdx.x >> 5;
    int lane = threadIdx.x & 31;
    int node = blockIdx.x * 8 + warp;
    if (node >= NNODES) return;

    float a[8];
#pragma unroll
    for (int i = 0; i < 8; i++) a[i] = 0.f;
    prop_gather(zin, node, lane, a);

    float r[8];
    blend_h0(node, lane, a, r);
    float4* op = (float4*)(dout + (size_t)node * FOUT);
    op[lane * 2]     = make_float4(r[0], r[1], r[2], r[3]);
    op[lane * 2 + 1] = make_float4(r[4], r[5], r[6], r[7]);
}

// ---------------- launch ----------------
extern "C" void kernel_launch(void* const* d_in, const int* in_sizes, int n_in,
                              void* d_out, int out_size) {
    const float* x  = 0;
    const void*  ei = 0;
    const float* W1 = 0;
    const float* b1 = 0;
    for (int i = 0; i < n_in; i++) {
        int sz = in_sizes[i];
        if      (sz == NNODES * FIN) x  = (const float*)d_in[i];
        else if (sz == 2 * NEDGES)   ei = d_in[i];
        else if (sz == FOUT * FIN)   W1 = (const float*)d_in[i];
        else if (sz == FOUT)         b1 = (const float*)d_in[i];
    }
    float* out = (float*)d_out;
    int N = NNODES;
    int E = NEDGES;

    k_detect<<<1, 256>>>((const int*)ei, E);
    k_zero<<<(N + 255) / 256, 256>>>(N);
    k_count<<<(E + 255) / 256, 256>>>(ei, E, N);
    k_dinv<<<(N + 255) / 256, 256>>>(N);
    int nb = (N + 255) / 256;
    k_scanA<<<nb, 256>>>(N);
    k_scanB<<<1, 512>>>(nb);
    k_scanC<<<(N + 255) / 256, 256>>>(N, E + N);
    k_scatter<<<(E + N + 255) / 256, 256>>>(ei, E, N);

    k_gemm_tc<<<(N + 127) / 128, 256>>>(x, W1, b1, N);

    // APPNP in fp16: step k writes (k even -> g_zh0, k odd -> g_zh1);
    // k=0 reads g_h0h; k=9 reads g_zh0 and writes fp32 d_out.
    int nprop = (N + 7) / 8;
    for (int k = 0; k < 9; k++) {
        int insel  = (k == 0) ? 0 : (((k - 1) & 1) ? 2 : 1);
        int outsel = (k & 1) ? 2 : 1;
        k_proph<<<nprop, 256>>>(insel, outsel);
    }
    k_propf<<<nprop, 256>>>(1, out);   // k=8 wrote g_zh0
}

// round 12
// speedup vs baseline: 1.2134x; 1.0321x over previous
#include <cuda_runtime.h>
#include <cuda_fp16.h>
#include <mma.h>

using namespace nvcuda;

#define NNODES 100000
#define NEDGES 3200000
#define FIN 512
#define FOUT 256
#define TOTE (NEDGES + NNODES)

// ---------------- scratch (device globals; zero-init bss) ----------------
__device__ __align__(16) __half g_h0h[(size_t)NNODES * FOUT];  // fp16 h0 (z0 + blend)
__device__ __align__(16) __half g_zh0[(size_t)NNODES * FOUT];  // fp16 ping
__device__ __align__(16) __half g_zh1[(size_t)NNODES * FOUT];  // fp16 pong
__device__ int   g_cnt[NNODES];
__device__ float g_dinv[NNODES];
__device__ int   g_rowptr[NNODES + 1];
__device__ int   g_fill[NNODES];
__device__ int   g_bsum[512];
__device__ __align__(16) int2 g_edge[TOTE];   // (src, norm-as-int)
__device__ int   g_is64;

// ---------------- edge dtype detection ----------------
__global__ void k_detect(const int* __restrict__ e32, int E) {
    __shared__ int nz;
    if (threadIdx.x == 0) nz = 0;
    __syncthreads();
    int lim = min(E, 65536);
    for (int i = threadIdx.x; i < lim; i += blockDim.x)
        if (e32[2 * i + 1] != 0) nz = 1;   // benign race
    __syncthreads();
    if (threadIdx.x == 0) g_is64 = (nz == 0) ? 1 : 0;
}

__device__ __forceinline__ int edge_at(const void* ei, long long idx) {
    if (g_is64) return (int)((const long long*)ei)[idx];
    return ((const int*)ei)[idx];
}

// ---------------- graph preprocessing ----------------
__global__ void k_zero(int n) {
    int i = blockIdx.x * blockDim.x + threadIdx.x;
    if (i < n) { g_cnt[i] = 0; g_fill[i] = 0; }
}

__global__ void k_count(const void* __restrict__ ei, int E, int n) {
    int i = blockIdx.x * blockDim.x + threadIdx.x;
    if (i < E) {
        int d = edge_at(ei, (long long)E + i);
        d = min(max(d, 0), n - 1);
        atomicAdd(&g_cnt[d], 1);
    }
}

__global__ void k_dinv(int n) {
    int i = blockIdx.x * blockDim.x + threadIdx.x;
    if (i < n) {
        int c = g_cnt[i] + 1;               // + self loop
        g_cnt[i] = c;
        g_dinv[i] = rsqrtf((float)c);
    }
}

__global__ void k_scanA(int n) {
    __shared__ int sh[256];
    int tid = threadIdx.x;
    int i = blockIdx.x * 256 + tid;
    int v = (i < n) ? g_cnt[i] : 0;
    sh[tid] = v;
    __syncthreads();
    for (int off = 1; off < 256; off <<= 1) {
        int t = (tid >= off) ? sh[tid - off] : 0;
        __syncthreads();
        sh[tid] += t;
        __syncthreads();
    }
    if (i < n) g_rowptr[i] = sh[tid] - v;
    if (tid == 255) g_bsum[blockIdx.x] = sh[255];
}

__global__ void k_scanB(int nb) {
    __shared__ int sh[512];
    int tid = threadIdx.x;
    int v = (tid < nb) ? g_bsum[tid] : 0;
    sh[tid] = v;
    __syncthreads();
    for (int off = 1; off < 512; off <<= 1) {
        int t = (tid >= off) ? sh[tid - off] : 0;
        __syncthreads();
        sh[tid] += t;
        __syncthreads();
    }
    g_bsum[tid] = sh[tid] - v;
}

__global__ void k_scanC(int n, int total) {
    int i = blockIdx.x * blockDim.x + threadIdx.x;
    if (i < n) g_rowptr[i] += g_bsum[i >> 8];
    if (i == 0) g_rowptr[n] = total;
}

__global__ void k_scatter(const void* __restrict__ ei, int E, int n) {
    int i = blockIdx.x * blockDim.x + threadIdx.x;
    int tot = E + n;
    if (i >= tot) return;
    int s, d;
    if (i < E) {
        s = edge_at(ei, i);
        d = edge_at(ei, (long long)E + i);
        s = min(max(s, 0), n - 1);
        d = min(max(d, 0), n - 1);
    } else {
        s = d = i - E;
    }
    int pos = g_rowptr[d] + atomicAdd(&g_fill[d], 1);
    pos = min(max(pos, 0), tot - 1);
    float w = g_dinv[s] * g_dinv[d];
    g_edge[pos] = make_int2(s, __float_as_int(w));
}

// -------- tensor-core GEMM + bias + L2-normalize*1.8 -> g_h0h (fp16) --------
// Block: 128 rows x 256 cols, 8 warps, each warp owns 16 full rows.
// BK=16; fp16 inputs (converted on stage-in), fp32 accumulate.
__global__ __launch_bounds__(256) void k_gemm_tc(const float* __restrict__ x,
                                                 const float* __restrict__ W,
                                                 const float* __restrict__ b,
                                                 int N) {
    __shared__ __align__(16) __half Ah[128][16];
    __shared__ __align__(16) __half Bh[256][16];
    __shared__ __align__(16) float  scr[8][256];   // per-warp 16x16 scratch
    __shared__ float bsh[256];

    int tid  = threadIdx.x;
    int w    = tid >> 5;
    int lane = tid & 31;
    int rows0 = blockIdx.x * 128;

    bsh[tid] = b[tid];

    wmma::fragment<wmma::accumulator, 16, 16, 16, float> acc[16];
#pragma unroll
    for (int n = 0; n < 16; n++) wmma::fill_fragment(acc[n], 0.0f);

    for (int k0 = 0; k0 < FIN; k0 += 16) {
        // stage x tile (128x16) -> fp16
        {
            int r = tid >> 1;
            int part = tid & 1;          // 0 or 1, 8 cols each
            int grow = rows0 + r;
            float4 v0 = make_float4(0.f, 0.f, 0.f, 0.f);
            float4 v1 = v0;
            if (grow < N) {
                const float* xp = &x[(size_t)grow * FIN + k0 + part * 8];
                v0 = *(const float4*)xp;
                v1 = *(const float4*)(xp + 4);
            }
            __half2 h0 = __floats2half2_rn(v0.x, v0.y);
            __half2 h1 = __floats2half2_rn(v0.z, v0.w);
            __half2 h2 = __floats2half2_rn(v1.x, v1.y);
            __half2 h3 = __floats2half2_rn(v1.z, v1.w);
            uint4 hv;
            hv.x = *(unsigned*)&h0; hv.y = *(unsigned*)&h1;
            hv.z = *(unsigned*)&h2; hv.w = *(unsigned*)&h3;
            *(uint4*)&Ah[r][part * 8] = hv;
        }
        // stage W tile (256x16) -> fp16
        {
            const float* wp = &W[(size_t)tid * FIN + k0];
            float4 w0 = *(const float4*)(wp);
            float4 w1 = *(const float4*)(wp + 4);
            float4 w2 = *(const float4*)(wp + 8);
            float4 w3 = *(const float4*)(wp + 12);
            __half2 h0 = __floats2half2_rn(w0.x, w0.y);
            __half2 h1 = __floats2half2_rn(w0.z, w0.w);
            __half2 h2 = __floats2half2_rn(w1.x, w1.y);
            __half2 h3 = __floats2half2_rn(w1.z, w1.w);
            __half2 h4 = __floats2half2_rn(w2.x, w2.y);
            __half2 h5 = __floats2half2_rn(w2.z, w2.w);
            __half2 h6 = __floats2half2_rn(w3.x, w3.y);
            __half2 h7 = __floats2half2_rn(w3.z, w3.w);
            uint4 a, c;
            a.x = *(unsigned*)&h0; a.y = *(unsigned*)&h1;
            a.z = *(unsigned*)&h2; a.w = *(unsigned*)&h3;
            c.x = *(unsigned*)&h4; c.y = *(unsigned*)&h5;
            c.z = *(unsigned*)&h6; c.w = *(unsigned*)&h7;
            *(uint4*)&Bh[tid][0] = a;
            *(uint4*)&Bh[tid][8] = c;
        }
        __syncthreads();

        wmma::fragment<wmma::matrix_a, 16, 16, 16, __half, wmma::row_major> af;
        wmma::load_matrix_sync(af, &Ah[w * 16][0], 16);
#pragma unroll
        for (int n = 0; n < 16; n++) {
            wmma::fragment<wmma::matrix_b, 16, 16, 16, __half, wmma::col_major> bf;
            wmma::load_matrix_sync(bf, &Bh[n * 16][0], 16);
            wmma::mma_sync(acc[n], af, bf, acc[n]);
        }
        __syncthreads();
    }

    // epilogue: bias + row L2 norm + scale, write fp16
    float* sc = scr[w];
    int lrow  = lane >> 1;          // 0..15 (warp-local row)
    int lcol0 = (lane & 1) * 8;     // 0 or 8 within 16-col frag
    float ssq = 0.0f;
#pragma unroll
    for (int n = 0; n < 16; n++) {
        wmma::store_matrix_sync(sc, acc[n], 16, wmma::mem_row_major);
        __syncwarp();
#pragma unroll
        for (int j = 0; j < 8; j++) {
            float v = sc[lrow * 16 + lcol0 + j] + bsh[n * 16 + lcol0 + j];
            ssq += v * v;
        }
        __syncwarp();
    }
    ssq += __shfl_xor_sync(0xffffffffu, ssq, 1);   // pair lanes complete the row
    float scale = 1.8f / fmaxf(sqrtf(ssq), 1e-12f);
    int grow = rows0 + w * 16 + lrow;
#pragma unroll
    for (int n = 0; n < 16; n++) {
        wmma::store_matrix_sync(sc, acc[n], 16, wmma::mem_row_major);
        __syncwarp();
        __half hv[8];
#pragma unroll
        for (int j = 0; j < 8; j++) {
            float v = (sc[lrow * 16 + lcol0 + j] + bsh[n * 16 + lcol0 + j]) * scale;
            hv[j] = __float2half_rn(v);
        }
        if (grow < N)
            *(uint4*)&g_h0h[(size_t)grow * FOUT + n * 16 + lcol0] = *(uint4*)hv;
        __syncwarp();
    }
}

// ---------------- APPNP step: one WARP per dst node, fp16 z ----------------
__device__ __forceinline__ void prop_gather(const __half* __restrict__ zin,
                                            int node, int lane,
                                            float acc[8]) {
    int beg = g_rowptr[node];
    int end = g_rowptr[node + 1];
    for (int base = beg; base < end; base += 32) {
        int idx = base + lane;
        int   s = 0;
        float w = 0.f;
        if (idx < end) {
            int2 t = g_edge[idx];
            s = t.x;
            w = __int_as_float(t.y);
        }
        int cnt = min(32, end - base);
        for (int j = 0; j < cnt; j++) {
            int   sj = __shfl_sync(0xffffffffu, s, j);
            float wj = __shfl_sync(0xffffffffu, w, j);
            uint4 v = *((const uint4*)(zin + (size_t)sj * FOUT) + lane);
            float2 f0 = __half22float2(*(__half2*)&v.x);
            float2 f1 = __half22float2(*(__half2*)&v.y);
            float2 f2 = __half22float2(*(__half2*)&v.z);
            float2 f3 = __half22float2(*(__half2*)&v.w);
            acc[0] += wj * f0.x; acc[1] += wj * f0.y;
            acc[2] += wj * f1.x; acc[3] += wj * f1.y;
            acc[4] += wj * f2.x; acc[5] += wj * f2.y;
            acc[6] += wj * f3.x; acc[7] += wj * f3.y;
        }
    }
}

__device__ __forceinline__ const __half* pick_h(int sel) {
    return sel == 0 ? g_h0h : (sel == 1 ? g_zh0 : g_zh1);
}

__device__ __forceinline__ void blend_h0(int node, int lane, float a[8],
                                         float r[8]) {
    uint4 hv = *((const uint4*)(g_h0h + (size_t)node * FOUT) + lane);
    float2 f0 = __half22float2(*(__half2*)&hv.x);
    float2 f1 = __half22float2(*(__half2*)&hv.y);
    float2 f2 = __half22float2(*(__half2*)&hv.z);
    float2 f3 = __half22float2(*(__half2*)&hv.w);
    r[0] = 0.85f * a[0] + 0.15f * f0.x;
    r[1] = 0.85f * a[1] + 0.15f * f0.y;
    r[2] = 0.85f * a[2] + 0.15f * f1.x;
    r[3] = 0.85f * a[3] + 0.15f * f1.y;
    r[4] = 0.85f * a[4] + 0.15f * f2.x;
    r[5] = 0.85f * a[5] + 0.15f * f2.y;
    r[6] = 0.85f * a[6] + 0.15f * f3.x;
    r[7] = 0.85f * a[7] + 0.15f * f3.y;
}

__global__ __launch_bounds__(256) void k_proph(int insel, int outsel) {
    const __half* zin = pick_h(insel);
    __half* zout = (outsel == 1) ? g_zh0 : g_zh1;
    int warp = threadIdx.x >> 5;
    int lane = threadIdx.x & 31;
    int node = blockIdx.x * 8 + warp;
    if (node >= NNODES) return;

    float a[8];
#pragma unroll
    for (int i = 0; i < 8; i++) a[i] = 0.f;
    prop_gather(zin, node, lane, a);

    float r[8];
    blend_h0(node, lane, a, r);
    __half2 h01 = __floats2half2_rn(r[0], r[1]);
    __half2 h23 = __floats2half2_rn(r[2], r[3]);
    __half2 h45 = __floats2half2_rn(r[4], r[5]);
    __half2 h67 = __floats2half2_rn(r[6], r[7]);
    uint4 hv;
    hv.x = *(unsigned*)&h01; hv.y = *(unsigned*)&h23;
    hv.z = *(unsigned*)&h45; hv.w = *(unsigned*)&h67;
    *((uint4*)(zout + (size_t)node * FOUT) + lane) = hv;
}

__global__ __launch_bounds__(256) void k_propf(int insel, float* __restrict__ dout) {
    const __half* zin = pick_h(insel);
    int warp = threadIdx.x >> 5;
    int lane = threadIdx.x & 31;
    int node = blockIdx.x * 8 + warp;
    if (node >= NNODES) return;

    float a[8];
#pragma unroll
    for (int i = 0; i < 8; i++) a[i] = 0.f;
    prop_gather(zin, node, lane, a);

    float r[8];
    blend_h0(node, lane, a, r);
    float4* op = (float4*)(dout + (size_t)node * FOUT);
    op[lane * 2]     = make_float4(r[0], r[1], r[2], r[3]);
    op[lane * 2 + 1] = make_float4(r[4], r[5], r[6], r[7]);
}

// ---------------- launch ----------------
extern "C" void kernel_launch(void* const* d_in, const int* in_sizes, int n_in,
                              void* d_out, int out_size) {
    const float* x  = 0;
    const void*  ei = 0;
    const float* W1 = 0;
    const float* b1 = 0;
    for (int i = 0; i < n_in; i++) {
        int sz = in_sizes[i];
        if      (sz == NNODES * FIN) x  = (const float*)d_in[i];
        else if (sz == 2 * NEDGES)   ei = d_in[i];
        else if (sz == FOUT * FIN)   W1 = (const float*)d_in[i];
        else if (sz == FOUT)         b1 = (const float*)d_in[i];
    }
    float* out = (float*)d_out;
    int N = NNODES;
    int E = NEDGES;

    // Lazily-created side stream + fork/join events (resource handles only;
    // identical launch sequence every call — work is deterministic).
    static cudaStream_t s_side = 0;
    static cudaEvent_t  ev_fork = 0, ev_join = 0;
    if (!s_side) {
        cudaStreamCreateWithFlags(&s_side, cudaStreamNonBlocking);
        cudaEventCreateWithFlags(&ev_fork, cudaEventDisableTiming);
        cudaEventCreateWithFlags(&ev_join, cudaEventDisableTiming);
    }

    // Fork: GEMM (independent of graph preprocessing) runs on the side stream.
    cudaEventRecord(ev_fork, 0);
    cudaStreamWaitEvent(s_side, ev_fork, 0);
    k_gemm_tc<<<(N + 127) / 128, 256, 0, s_side>>>(x, W1, b1, N);
    cudaEventRecord(ev_join, s_side);

    // Main stream: graph preprocessing chain (overlaps with GEMM).
    k_detect<<<1, 256>>>((const int*)ei, E);
    k_zero<<<(N + 255) / 256, 256>>>(N);
    k_count<<<(E + 255) / 256, 256>>>(ei, E, N);
    k_dinv<<<(N + 255) / 256, 256>>>(N);
    int nb = (N + 255) / 256;
    k_scanA<<<nb, 256>>>(N);
    k_scanB<<<1, 512>>>(nb);
    k_scanC<<<(N + 255) / 256, 256>>>(N, E + N);
    k_scatter<<<(E + N + 255) / 256, 256>>>(ei, E, N);

    // Join: prop needs both g_h0h (GEMM) and the CSR (preproc).
    cudaStreamWaitEvent(0, ev_join, 0);

    // APPNP in fp16: step k writes (k even -> g_zh0, k odd -> g_zh1);
    // k=0 reads g_h0h; k=9 reads g_zh0 and writes fp32 d_out.
    int nprop = (N + 7) / 8;
    for (int k = 0; k < 9; k++) {
        int insel  = (k == 0) ? 0 : (((k - 1) & 1) ? 2 : 1);
        int outsel = (k & 1) ? 2 : 1;
        k_proph<<<nprop, 256>>>(insel, outsel);
    }
    k_propf<<<nprop, 256>>>(1, out);   // k=8 wrote g_zh0
}